// round 4
// baseline (speedup 1.0000x reference)
#include <cuda_runtime.h>

// Math collapse: K and V rows are identical across the sequence dim (age is
// broadcast before the K/V projections), so every score row is constant,
// softmax weights are exactly 1/N, and attended[b,n,:] == age[b]@Wv + bv.
// Output = pixel + broadcast(age @ Wv + bv) over the n dimension.

#define B_DIM 8
#define N_DIM 2048
#define D_DIM 768
#define A_DIM 128

__device__ __align__(16) float g_vb[B_DIM * D_DIM];

// vb[b][d] = sum_a age[b][a] * Wv[a][d] + bv[d]   (6144 outputs, ~2 us)
__global__ void compute_vb_kernel(const float* __restrict__ age,
                                  const float* __restrict__ Wv,
                                  const float* __restrict__ bv) {
    int idx = blockIdx.x * blockDim.x + threadIdx.x;   // 0 .. 6143
    if (idx >= B_DIM * D_DIM) return;
    int b = idx / D_DIM;
    int d = idx - b * D_DIM;
    const float* a = age + b * A_DIM;
    float acc = bv[d];
#pragma unroll 8
    for (int i = 0; i < A_DIM; i++) {
        acc = fmaf(a[i], Wv[i * D_DIM + d], acc);      // coalesced across d
    }
    g_vb[idx] = acc;
}

// out[b,n,d] = pixel[b,n,d] + vb[b,d]
// grid = (384, B), block = 256; each thread handles one float4.
// Per batch: N*D/4 = 393216 float4 = 384 blocks * 256 threads * 4 exactly? No:
// 384*256 = 98304, so each thread strides 4 times (x4 ILP for MLP).
__global__ void add_broadcast_kernel(const float4* __restrict__ pixel,
                                     float4* __restrict__ out) {
    const int per_batch4 = N_DIM * D_DIM / 4;           // 393216
    const int b = blockIdx.y;
    const int base = b * per_batch4;
    const float4* __restrict__ vb4 =
        reinterpret_cast<const float4*>(&g_vb[b * D_DIM]);

    int i4 = blockIdx.x * blockDim.x + threadIdx.x;     // 0 .. 98303
    const int stride = gridDim.x * blockDim.x;          // 98304

#pragma unroll 4
    for (int s = 0; s < 4; s++, i4 += stride) {
        int d4 = i4 % (D_DIM / 4);                      // const-mod -> mul/shift
        float4 p = pixel[base + i4];
        float4 v = vb4[d4];
        p.x += v.x; p.y += v.y; p.z += v.z; p.w += v.w;
        out[base + i4] = p;
    }
}

extern "C" void kernel_launch(void* const* d_in, const int* in_sizes, int n_in,
                              void* d_out, int out_size) {
    // metadata order: pixel_features, age_features, Wq, bq, Wk, bk, Wv, bv
    const float* pixel = (const float*)d_in[0];
    const float* age   = (const float*)d_in[1];
    const float* Wv    = (const float*)d_in[6];
    const float* bv    = (const float*)d_in[7];
    float* out = (float*)d_out;

    compute_vb_kernel<<<(B_DIM * D_DIM + 255) / 256, 256>>>(age, Wv, bv);

    dim3 grid(384, B_DIM);
    add_broadcast_kernel<<<grid, 256>>>((const float4*)pixel, (float4*)out);
}

// round 5
// speedup vs baseline: 1.3367x; 1.3367x over previous
#include <cuda_runtime.h>

// Math collapse: K and V rows are identical across the sequence dim (age is
// broadcast before the K/V projections), so every score row is constant,
// softmax weights are exactly 1/N, and attended[b,n,:] == age[b]@Wv + bv.
// Output = pixel + broadcast(age @ Wv + bv) over the n dimension.
//
// Fully fused single kernel: each block recomputes vb[b,:] into shared memory
// (Wv is 393KB -> L2-resident; 128 blocks of redundant reads ~= 50MB L2
// traffic, cheap next to the 100MB HBM stream), then streams its n-slice of
// out = pixel + vb.

#define B_DIM 8
#define N_DIM 2048
#define D_DIM 768
#define A_DIM 128
#define NCH   16                       // n-chunks per batch -> 16*8 = 128 blocks
#define NROWS (N_DIM / NCH)            // 128 rows per block
#define TPB   1024

__global__ __launch_bounds__(TPB, 1)
void fused_cross_attn_kernel(const float* __restrict__ pixel,
                             const float* __restrict__ age,
                             const float* __restrict__ Wv,
                             const float* __restrict__ bv,
                             float* __restrict__ out) {
    __shared__ __align__(16) float s_age[A_DIM];
    __shared__ __align__(16) float s_vb[D_DIM];

    const int b   = blockIdx.y;
    const int tid = threadIdx.x;

    if (tid < A_DIM) s_age[tid] = age[b * A_DIM + tid];
    __syncthreads();

    // ---- preamble: vb[d] = sum_a age[b][a]*Wv[a][d] + bv[d], threads 0..767
    if (tid < D_DIM) {
        const int d = tid;
        const float4* __restrict__ a4 = reinterpret_cast<const float4*>(s_age);
        float acc0 = bv[d], acc1 = 0.f, acc2 = 0.f, acc3 = 0.f;
#pragma unroll
        for (int i = 0; i < A_DIM / 4; i++) {
            float4 a = a4[i];
            const float* __restrict__ w = Wv + (4 * i) * D_DIM + d;
            acc0 = fmaf(a.x, w[0 * D_DIM], acc0);
            acc1 = fmaf(a.y, w[1 * D_DIM], acc1);
            acc2 = fmaf(a.z, w[2 * D_DIM], acc2);
            acc3 = fmaf(a.w, w[3 * D_DIM], acc3);
        }
        s_vb[d] = (acc0 + acc1) + (acc2 + acc3);
    }
    __syncthreads();

    // ---- stream: out[b, n0:n0+NROWS, :] = pixel + vb
    const int n0    = blockIdx.x * NROWS;
    const long long base4 = ((long long)b * N_DIM + n0) * (D_DIM / 4);
    const float4* __restrict__ p4 = reinterpret_cast<const float4*>(pixel) + base4;
    float4* __restrict__       o4 = reinterpret_cast<float4*>(out) + base4;
    const float4* __restrict__ v4 = reinterpret_cast<const float4*>(s_vb);

    const int total4 = NROWS * (D_DIM / 4);             // 24576
#pragma unroll 8
    for (int i4 = tid; i4 < total4; i4 += TPB) {
        int d4 = i4 % (D_DIM / 4);                      // const-mod -> mul/shift
        float4 p = p4[i4];
        float4 v = v4[d4];                              // conflict-free LDS.128
        p.x += v.x; p.y += v.y; p.z += v.z; p.w += v.w;
        o4[i4] = p;
    }
}

extern "C" void kernel_launch(void* const* d_in, const int* in_sizes, int n_in,
                              void* d_out, int out_size) {
    // metadata order: pixel_features, age_features, Wq, bq, Wk, bk, Wv, bv
    const float* pixel = (const float*)d_in[0];
    const float* age   = (const float*)d_in[1];
    const float* Wv    = (const float*)d_in[6];
    const float* bv    = (const float*)d_in[7];
    float* out = (float*)d_out;

    dim3 grid(NCH, B_DIM);
    fused_cross_attn_kernel<<<grid, TPB>>>(pixel, age, Wv, bv, out);
}

// round 6
// speedup vs baseline: 1.4962x; 1.1193x over previous
#include <cuda_runtime.h>

// Math collapse: K and V rows are identical across the sequence dim (age is
// broadcast before the K/V projections), so every score row is constant,
// softmax weights are exactly 1/N, and attended[b,n,:] == age[b]@Wv + bv.
// Output = pixel + broadcast(age @ Wv + bv) over n.
//
// Fused single kernel, sharded 3 ways: (d-chunk, n-chunk, batch). Each block
// computes only its 96-column slice of vb (49KB of Wv -> 12.6MB total L2
// traffic across 256 blocks) via split-K x4 in the preamble, then streams
// its (n-rows x 96-cols) tile of out = pixel + vb.

#define B_DIM 8
#define N_DIM 2048
#define D_DIM 768
#define A_DIM 128

#define DCH   8                        // d-chunks -> 96 floats (24 float4) each
#define NCH   4                        // n-chunks -> 512 rows each
#define DSUB  (D_DIM / DCH)            // 96
#define DSUB4 (DSUB / 4)               // 24
#define NROWS (N_DIM / NCH)            // 512
#define TPB   512
#define KSPL  4                        // split-K ways in preamble

__global__ __launch_bounds__(TPB, 2)
void fused_cross_attn_kernel(const float* __restrict__ pixel,
                             const float* __restrict__ age,
                             const float* __restrict__ Wv,
                             const float* __restrict__ bv,
                             float* __restrict__ out) {
    __shared__ __align__(16) float s_age[A_DIM];
    __shared__ __align__(16) float s_part[KSPL * DSUB];
    __shared__ __align__(16) float s_vb[DSUB];

    const int tid = threadIdx.x;
    const int dch = blockIdx.x;        // 0..7
    const int nch = blockIdx.y;        // 0..3
    const int b   = blockIdx.z;        // 0..7
    const int d0  = dch * DSUB;

    if (tid < A_DIM) s_age[tid] = age[b * A_DIM + tid];
    __syncthreads();

    // ---- preamble: vb[d0+dl] = sum_a age[b][a]*Wv[a][d0+dl] + bv[d0+dl]
    // split-K x4: 384 threads, each a 32-length partial dot (all loads in flight)
    if (tid < KSPL * DSUB) {
        const int dl = tid % DSUB;     // consecutive threads -> coalesced Wv
        const int k  = tid / DSUB;     // 0..3
        const int dg = d0 + dl;
        float acc = 0.f;
#pragma unroll
        for (int i = 0; i < A_DIM / KSPL; i++) {
            const int a = k * (A_DIM / KSPL) + i;
            acc = fmaf(s_age[a], Wv[a * D_DIM + dg], acc);
        }
        s_part[k * DSUB + dl] = acc;
    }
    __syncthreads();
    if (tid < DSUB) {
        s_vb[tid] = bv[d0 + tid] + ((s_part[tid] + s_part[DSUB + tid]) +
                    (s_part[2 * DSUB + tid] + s_part[3 * DSUB + tid]));
    }
    __syncthreads();

    // ---- stream: out[b, n0:n0+NROWS, d0:d0+DSUB] = pixel + vb
    const int n0 = nch * NROWS;
    const int base4 = ((b * N_DIM + n0) * D_DIM + d0) / 4;   // fits in int
    const float4* __restrict__ p4 = reinterpret_cast<const float4*>(pixel) + base4;
    float4* __restrict__       o4 = reinterpret_cast<float4*>(out) + base4;
    const float4* __restrict__ v4 = reinterpret_cast<const float4*>(s_vb);

    const int row_stride4 = D_DIM / 4;                        // 192
    const int total4 = NROWS * DSUB4;                         // 12288
#pragma unroll 8
    for (int i4 = tid; i4 < total4; i4 += TPB) {
        const int row = i4 / DSUB4;                           // const-div
        const int c   = i4 - row * DSUB4;                     // 0..23
        const int a   = row * row_stride4 + c;
        float4 p = p4[a];
        float4 v = v4[c];
        p.x += v.x; p.y += v.y; p.z += v.z; p.w += v.w;
        o4[a] = p;
    }
}

extern "C" void kernel_launch(void* const* d_in, const int* in_sizes, int n_in,
                              void* d_out, int out_size) {
    // metadata order: pixel_features, age_features, Wq, bq, Wk, bk, Wv, bv
    const float* pixel = (const float*)d_in[0];
    const float* age   = (const float*)d_in[1];
    const float* Wv    = (const float*)d_in[6];
    const float* bv    = (const float*)d_in[7];
    float* out = (float*)d_out;

    dim3 grid(DCH, NCH, B_DIM);
    fused_cross_attn_kernel<<<grid, TPB>>>(pixel, age, Wv, bv, out);
}